// round 4
// baseline (speedup 1.0000x reference)
#include <cuda_runtime.h>
#include <cuda_bf16.h>
#include <math.h>

// Problem: B=4, N=1024, H=64
// Inputs (metadata order): x (B,N,H) f32, W1 (H,2H) f32, b1 (H) f32, W2 (1,H) f32, b2 (1) f32
// Outputs: updated (B,N,H) f32 then attn (B,N,N) f32, concatenated in d_out.

#define Bk 4
#define Nk 1024
#define Hk 64
#define TI 16
#define TJ 64

// scratch: A[b,i,h] = x@W1a^T + b1 ; C[b,j,h] = x@W1b^T
__device__ float g_A[Bk * Nk * Hk];
__device__ float g_C[Bk * Nk * Hk];

// ---------------------------------------------------------------------------
// K1: compute A and C.   grid = B*N/16 blocks, 128 threads.
//   A[row,h] = sum_d x[row,d] * W1[h, d]       (h = col, col<64)
//   C[row,h] = sum_d x[row,d] * W1[h, 64 + d]  (col = 64+h)
// ---------------------------------------------------------------------------
__global__ __launch_bounds__(128) void k1_proj(const float* __restrict__ x,
                                               const float* __restrict__ W1,
                                               const float* __restrict__ b1)
{
    __shared__ float w1t[64 * 130];   // w1t[d][col], padded stride 130
    __shared__ float xs[16][64];

    const int t = threadIdx.x;
    const int row0 = blockIdx.x * 16;

    // Load & transpose W1: w1t[d][col] = W1[h_col, off_col + d]
    for (int idx = t; idx < 64 * 128; idx += 128) {
        const int r = idx >> 7;      // W1 row (= h)
        const int c = idx & 127;     // W1 col
        const int d = c & 63;
        const int col = (c < 64) ? r : (64 + r);
        w1t[d * 130 + col] = W1[idx];
    }
    // Load 16 x-rows
    for (int idx = t; idx < 16 * 64; idx += 128)
        xs[idx >> 6][idx & 63] = x[row0 * 64 + idx];
    __syncthreads();

    const int col = t;                     // 0..127
    const int h = col & 63;
    const float bias = (col < 64) ? b1[h] : 0.0f;
    float* dst = (col < 64) ? g_A : g_C;

    for (int r = 0; r < 16; r++) {
        float acc = bias;
#pragma unroll
        for (int d = 0; d < 64; d++)
            acc = fmaf(xs[r][d], w1t[d * 130 + col], acc);
        dst[(row0 + r) * 64 + h] = acc;
    }
}

// ---------------------------------------------------------------------------
// K2: logits + softmax + attn write + updated = attn @ x
// grid = B * N/TI = 256 blocks, 256 threads.
// Thread mapping: il = t>>4 (local i row), jl = t&15.
// ---------------------------------------------------------------------------
__global__ __launch_bounds__(256) void k2_attn(const float* __restrict__ x,
                                               const float* __restrict__ W2,
                                               const float* __restrict__ b2,
                                               float* __restrict__ upd,
                                               float* __restrict__ attn)
{
    __shared__ float Cs[TJ * 65];     // padded C tile
    __shared__ float xs[TJ * 68];     // padded x tile (float4-aligned rows)
    __shared__ float ps[TI * 65];     // probabilities tile
    __shared__ float w2s[64];

    const int t = threadIdx.x;
    const int blk = blockIdx.x;          // 0..255
    const int b = blk >> 6;              // 64 i-tiles per batch
    const int i0 = (blk & 63) * TI;

    if (t < 64) w2s[t] = W2[t];
    const float b2v = b2[0];

    const int il = t >> 4;               // 0..15
    const int jl = t & 15;                // 0..15
    const int row = b * Nk + i0 + il;

    // A row for this thread's i into registers
    float areg[64];
#pragma unroll
    for (int h = 0; h < 64; h++) areg[h] = g_A[row * 64 + h];

    const float* __restrict__ Cb = g_C + b * Nk * 64;
    float* __restrict__ lrow = attn + row * Nk;

    float m = -1e30f, s = 0.0f;

    // ---------------- Phase 1: logits + online (m, s) ----------------
    for (int jt = 0; jt < Nk; jt += TJ) {
        __syncthreads();
#pragma unroll
        for (int q = 0; q < (TJ * 64) / 256; q++) {
            const int idx = q * 256 + t;
            Cs[(idx >> 6) * 65 + (idx & 63)] = Cb[jt * 64 + idx];
        }
        __syncthreads();

        float acc[4] = {0.f, 0.f, 0.f, 0.f};
#pragma unroll
        for (int h = 0; h < 64; h++) {
            const float a = areg[h];
            const float w = w2s[h];
#pragma unroll
            for (int k = 0; k < 4; k++) {
                float v = a + Cs[(jl + 16 * k) * 65 + h];
                v = fmaxf(v, 0.0f);
                acc[k] = fmaf(v, w, acc[k]);
            }
        }
#pragma unroll
        for (int k = 0; k < 4; k++) {
            const float l = acc[k] + b2v;
            lrow[jt + jl + 16 * k] = l;        // raw logit (temp storage)
            const float mn = fmaxf(m, l);
            s = s * __expf(m - mn) + __expf(l - mn);
            m = mn;
        }
    }

    // merge (m,s) across the 16 threads that share il (contiguous lanes)
#pragma unroll
    for (int off = 1; off < 16; off <<= 1) {
        const float mo = __shfl_xor_sync(0xffffffffu, m, off);
        const float so = __shfl_xor_sync(0xffffffffu, s, off);
        const float mn = fmaxf(m, mo);
        s = s * __expf(m - mn) + so * __expf(mo - mn);
        m = mn;
    }
    const float inv_s = 1.0f / s;

    // ---------------- Phase 2: attn normalize + updated = attn @ x ----------
    const int dg = jl;                    // d-group: d = 4*dg .. 4*dg+3
    float4 a4 = make_float4(0.f, 0.f, 0.f, 0.f);
    const float* __restrict__ xb = x + b * Nk * 64;

    for (int jt = 0; jt < Nk; jt += TJ) {
        __syncthreads();
#pragma unroll
        for (int q = 0; q < (TJ * 64) / 256; q++) {
            const int idx = q * 256 + t;
            xs[(idx >> 6) * 68 + (idx & 63)] = xb[jt * 64 + idx];
        }
#pragma unroll
        for (int k = 0; k < 4; k++) {
            const int jloc = jl + 16 * k;
            const float l = lrow[jt + jloc];
            const float p = __expf(l - m) * inv_s;
            ps[il * 65 + jloc] = p;
            lrow[jt + jloc] = p;              // final normalized attn
        }
        __syncthreads();

#pragma unroll
        for (int j = 0; j < TJ; j++) {
            const float pv = ps[il * 65 + j];
            const float4 xv = *reinterpret_cast<const float4*>(&xs[j * 68 + dg * 4]);
            a4.x = fmaf(pv, xv.x, a4.x);
            a4.y = fmaf(pv, xv.y, a4.y);
            a4.z = fmaf(pv, xv.z, a4.z);
            a4.w = fmaf(pv, xv.w, a4.w);
        }
    }
    *reinterpret_cast<float4*>(&upd[row * 64 + dg * 4]) = a4;
}

// ---------------------------------------------------------------------------
extern "C" void kernel_launch(void* const* d_in, const int* in_sizes, int n_in,
                              void* d_out, int out_size)
{
    const float* x  = (const float*)d_in[0];
    const float* W1 = (const float*)d_in[1];
    const float* b1 = (const float*)d_in[2];
    const float* W2 = (const float*)d_in[3];
    const float* b2 = (const float*)d_in[4];

    float* upd  = (float*)d_out;                     // (B,N,H)
    float* attn = (float*)d_out + Bk * Nk * Hk;      // (B,N,N)

    k1_proj<<<(Bk * Nk) / 16, 128>>>(x, W1, b1);
    k2_attn<<<Bk * (Nk / TI), 256>>>(x, W2, b2, upd, attn);
}

// round 5
// speedup vs baseline: 1.3096x; 1.3096x over previous
#include <cuda_runtime.h>
#include <math.h>

// B=4, N=1024, H=64
// in: x (B,N,H) f32, W1 (H,2H) f32, b1 (H) f32, W2 (1,H) f32, b2 (1) f32
// out: updated (B,N,H) f32 ++ attn (B,N,N) f32

#define Bk 4
#define Nk 1024
#define Hk 64

// scratch
__device__ float g_A[Bk * Nk * Hk];    // A[b*N+i][h] = x@W1a^T + b1
__device__ float g_Ct[Bk * Hk * Nk];   // C^T: [b][h][j] = (x@W1b^T)[j][h]

// ---------------------------------------------------------------------------
// K1: projections. grid = B*N/16, 128 threads.
// ---------------------------------------------------------------------------
__global__ __launch_bounds__(128) void k1_proj(const float* __restrict__ x,
                                               const float* __restrict__ W1,
                                               const float* __restrict__ b1)
{
    __shared__ float w1t[64 * 130];   // w1t[d][col]
    __shared__ float xs[16][64];
    __shared__ float sc[64 * 17];     // C staging for transposed writeout

    const int t = threadIdx.x;
    const int row0 = blockIdx.x * 16;
    const int b = row0 >> 10;
    const int j0 = row0 & 1023;

    for (int idx = t; idx < 64 * 128; idx += 128) {
        const int r = idx >> 7;      // W1 row (= h)
        const int c = idx & 127;     // W1 col
        const int d = c & 63;
        const int col = (c < 64) ? r : (64 + r);
        w1t[d * 130 + col] = W1[idx];
    }
    for (int idx = t; idx < 16 * 64; idx += 128)
        xs[idx >> 6][idx & 63] = x[row0 * 64 + idx];
    __syncthreads();

    const int col = t;
    const int h = col & 63;
    const float bias = (col < 64) ? b1[h] : 0.0f;

    for (int r = 0; r < 16; r++) {
        float acc = bias;
#pragma unroll
        for (int d = 0; d < 64; d++)
            acc = fmaf(xs[r][d], w1t[d * 130 + col], acc);
        if (col < 64) g_A[(row0 + r) * 64 + h] = acc;
        else          sc[h * 17 + r] = acc;
    }
    __syncthreads();

#pragma unroll
    for (int q = 0; q < 8; q++) {
        const int e = t * 8 + q;
        const int h2 = e >> 4, jl = e & 15;
        g_Ct[b * 65536 + h2 * 1024 + j0 + jl] = sc[h2 * 17 + jl];
    }
}

// ---------------------------------------------------------------------------
// K2: logits + softmax + attn + updated.  grid = B*64 = 256 blocks, 256 thr.
// Phase 1 thread tile: 4i x 4j  (ti = t>>6 -> 4 rows, tj = t&63 -> 4 cols)
// Dynamic smem layout (floats):
//   buf  [16384] : Ct tile [64][256] (phase1) / x tile [256][64] (phase2)
//   ps   [4096]  : prob tile [16][256]
//   At   [1280]  : A^T tile [64][20]
//   w2s  [64], redm[32], reds[32], smm[16], sis[16]
// ---------------------------------------------------------------------------
__global__ __launch_bounds__(256, 2) void k2_attn(const float* __restrict__ x,
                                                  const float* __restrict__ W2,
                                                  const float* __restrict__ b2,
                                                  float* __restrict__ upd,
                                                  float* __restrict__ attn)
{
    extern __shared__ float sm[];
    float* buf  = sm;               // 16384
    float* ps   = sm + 16384;       // 4096
    float* At   = sm + 20480;       // 1280
    float* w2s  = At + 1280;        // 64
    float* redm = w2s + 64;         // 32
    float* reds = redm + 32;        // 32
    float* smm  = reds + 32;        // 16
    float* sis  = smm + 16;         // 16

    const int t  = threadIdx.x;
    const int b  = blockIdx.x >> 6;
    const int i0 = (blockIdx.x & 63) * 16;
    const int ti = t >> 6;            // 0..3
    const int tj = t & 63;            // 0..63
    const float b2v = b2[0];

    if (t < 64) w2s[t] = W2[t];
    {   // transpose A tile into At[h][i] (padded stride 20, float4-aligned rows)
        const int il = t >> 4, h0 = (t & 15) * 4;
        float4 a4 = *(const float4*)&g_A[(b * Nk + i0 + il) * 64 + h0];
        At[(h0 + 0) * 20 + il] = a4.x;
        At[(h0 + 1) * 20 + il] = a4.y;
        At[(h0 + 2) * 20 + il] = a4.z;
        At[(h0 + 3) * 20 + il] = a4.w;
    }

    float m[4] = {-1e30f, -1e30f, -1e30f, -1e30f};
    float s[4] = {0.f, 0.f, 0.f, 0.f};

    const float* __restrict__ Ctb = g_Ct + b * 65536;
    float* __restrict__ attb = attn + (b * Nk + i0) * Nk;

    // ---------------- Phase 1: logits + online (m, s) ----------------
    for (int pass = 0; pass < 4; pass++) {
        const int jt = pass * 256;
        __syncthreads();
#pragma unroll
        for (int q = 0; q < 16; q++) {
            const int idx4 = q * 256 + t;
            const int row = idx4 >> 6, c4 = idx4 & 63;
            *(float4*)&buf[row * 256 + c4 * 4] =
                *(const float4*)&Ctb[row * 1024 + jt + c4 * 4];
        }
        __syncthreads();

        float acc[4][4] = {};
#pragma unroll 8
        for (int h = 0; h < 64; h++) {
            const float4 a4 = *(const float4*)&At[h * 20 + ti * 4];
            const float4 c4 = *(const float4*)&buf[h * 256 + tj * 4];
            const float w = w2s[h];
            const float va[4] = {a4.x, a4.y, a4.z, a4.w};
            const float vc[4] = {c4.x, c4.y, c4.z, c4.w};
#pragma unroll
            for (int ii = 0; ii < 4; ii++)
#pragma unroll
                for (int jj = 0; jj < 4; jj++) {
                    const float v = fmaxf(va[ii] + vc[jj], 0.0f);
                    acc[ii][jj] = fmaf(v, w, acc[ii][jj]);
                }
        }

#pragma unroll
        for (int ii = 0; ii < 4; ii++) {
            float4 l4;
            l4.x = acc[ii][0] + b2v;
            l4.y = acc[ii][1] + b2v;
            l4.z = acc[ii][2] + b2v;
            l4.w = acc[ii][3] + b2v;
            *(float4*)&attb[(ti * 4 + ii) * Nk + jt + tj * 4] = l4;  // raw logits
            const float lm = fmaxf(fmaxf(l4.x, l4.y), fmaxf(l4.z, l4.w));
            const float mn = fmaxf(m[ii], lm);
            s[ii] = s[ii] * __expf(m[ii] - mn)
                  + __expf(l4.x - mn) + __expf(l4.y - mn)
                  + __expf(l4.z - mn) + __expf(l4.w - mn);
            m[ii] = mn;
        }
    }

    // reduce (m,s) over 32 lanes (all share ti, disjoint j)
#pragma unroll
    for (int off = 16; off > 0; off >>= 1) {
#pragma unroll
        for (int ii = 0; ii < 4; ii++) {
            const float mo = __shfl_xor_sync(0xffffffffu, m[ii], off);
            const float so = __shfl_xor_sync(0xffffffffu, s[ii], off);
            const float mn = fmaxf(m[ii], mo);
            s[ii] = s[ii] * __expf(m[ii] - mn) + so * __expf(mo - mn);
            m[ii] = mn;
        }
    }
    const int w = t >> 5, lane = t & 31;
    if (lane == 0) {
#pragma unroll
        for (int ii = 0; ii < 4; ii++) { redm[w * 4 + ii] = m[ii]; reds[w * 4 + ii] = s[ii]; }
    }
    __syncthreads();
    if (t < 16) {   // combine the 2 warps per ti; row r = t
        const int w0 = (t >> 2) * 2, ii = t & 3;
        const float m0 = redm[w0 * 4 + ii], m1 = redm[(w0 + 1) * 4 + ii];
        const float mn = fmaxf(m0, m1);
        const float ss = reds[w0 * 4 + ii] * __expf(m0 - mn)
                       + reds[(w0 + 1) * 4 + ii] * __expf(m1 - mn);
        smm[t] = mn;
        sis[t] = 1.0f / ss;
    }
    __syncthreads();

    // ---------------- Phase 2: normalize attn + updated = attn @ x ----------
    const int il = t >> 4, dg = t & 15;
    const float* __restrict__ xb = x + b * Nk * 64;
    float4 u = make_float4(0.f, 0.f, 0.f, 0.f);
    float mreg[4], sreg[4];
#pragma unroll
    for (int ii = 0; ii < 4; ii++) { mreg[ii] = smm[ti * 4 + ii]; sreg[ii] = sis[ti * 4 + ii]; }

    for (int pass = 0; pass < 4; pass++) {
        const int jt = pass * 256;
        __syncthreads();
#pragma unroll
        for (int q = 0; q < 16; q++) {
            const int idx4 = q * 256 + t;
            const int j = idx4 >> 4, d4 = idx4 & 15;
            *(float4*)&buf[j * 64 + d4 * 4] =
                *(const float4*)&xb[(jt + j) * 64 + d4 * 4];
        }
#pragma unroll
        for (int ii = 0; ii < 4; ii++) {
            const int rl = ti * 4 + ii;
            float4 l4 = *(const float4*)&attb[rl * Nk + jt + tj * 4];  // own writes
            const float mi = mreg[ii], si = sreg[ii];
            float4 p;
            p.x = __expf(l4.x - mi) * si;
            p.y = __expf(l4.y - mi) * si;
            p.z = __expf(l4.z - mi) * si;
            p.w = __expf(l4.w - mi) * si;
            *(float4*)&attb[rl * Nk + jt + tj * 4] = p;                // final attn
            *(float4*)&ps[rl * 256 + tj * 4] = p;
        }
        __syncthreads();

        const float* __restrict__ psr = ps + il * 256;
#pragma unroll 8
        for (int j = 0; j < 256; j++) {
            const float pv = psr[j];
            const float4 x4 = *(const float4*)&buf[j * 64 + dg * 4];
            u.x = fmaf(pv, x4.x, u.x);
            u.y = fmaf(pv, x4.y, u.y);
            u.z = fmaf(pv, x4.z, u.z);
            u.w = fmaf(pv, x4.w, u.w);
        }
    }
    *(float4*)&upd[(b * Nk + i0 + il) * 64 + dg * 4] = u;
}

// ---------------------------------------------------------------------------
extern "C" void kernel_launch(void* const* d_in, const int* in_sizes, int n_in,
                              void* d_out, int out_size)
{
    const float* x  = (const float*)d_in[0];
    const float* W1 = (const float*)d_in[1];
    const float* b1 = (const float*)d_in[2];
    const float* W2 = (const float*)d_in[3];
    const float* b2 = (const float*)d_in[4];

    float* upd  = (float*)d_out;                    // (B,N,H)
    float* attn = (float*)d_out + Bk * Nk * Hk;     // (B,N,N)

    cudaFuncSetAttribute(k2_attn, cudaFuncAttributeMaxDynamicSharedMemorySize, 87680);

    k1_proj<<<(Bk * Nk) / 16, 128>>>(x, W1, b1);
    k2_attn<<<Bk * 64, 256, 87680>>>(x, W2, b2, upd, attn);
}

// round 6
// speedup vs baseline: 1.5905x; 1.2146x over previous
#include <cuda_runtime.h>
#include <math.h>

// B=4, N=1024, H=64
// in: x (B,N,H) f32, W1 (H,2H) f32, b1 (H) f32, W2 (1,H) f32, b2 (1) f32
// out: updated (B,N,H) f32 ++ attn (B,N,N) f32

#define Bk 4
#define Nk 1024

// scratch
__device__ float g_A[Bk * Nk * 64];    // A[b*N+i][h] = x@W1a^T + b1
__device__ float g_Ct[Bk * 64 * Nk];   // C^T: [b][h][j]

union F2U { float2 f2; unsigned long long u; float f[2]; };

__device__ __forceinline__ unsigned long long add2(unsigned long long a, unsigned long long b) {
    unsigned long long r;
    asm("add.rn.f32x2 %0, %1, %2;" : "=l"(r) : "l"(a), "l"(b));
    return r;
}
__device__ __forceinline__ unsigned long long fma2(unsigned long long a, unsigned long long b,
                                                   unsigned long long c) {
    unsigned long long r;
    asm("fma.rn.f32x2 %0, %1, %2, %3;" : "=l"(r) : "l"(a), "l"(b), "l"(c));
    return r;
}

// ---------------------------------------------------------------------------
// K1: projections. grid = B*N/16, 128 threads.
// ---------------------------------------------------------------------------
__global__ __launch_bounds__(128) void k1_proj(const float* __restrict__ x,
                                               const float* __restrict__ W1,
                                               const float* __restrict__ b1)
{
    __shared__ float w1t[64 * 130];   // w1t[d][col]
    __shared__ float xs[16][64];
    __shared__ float sc[64 * 17];     // C staging for transposed writeout

    const int t = threadIdx.x;
    const int row0 = blockIdx.x * 16;
    const int b = row0 >> 10;
    const int j0 = row0 & 1023;

    for (int idx = t; idx < 64 * 128; idx += 128) {
        const int r = idx >> 7;
        const int c = idx & 127;
        const int d = c & 63;
        const int col = (c < 64) ? r : (64 + r);
        w1t[d * 130 + col] = W1[idx];
    }
    for (int idx = t; idx < 16 * 64; idx += 128)
        xs[idx >> 6][idx & 63] = x[row0 * 64 + idx];
    __syncthreads();

    const int col = t;
    const int h = col & 63;
    const float bias = (col < 64) ? b1[h] : 0.0f;

    for (int r = 0; r < 16; r++) {
        float acc = bias;
#pragma unroll
        for (int d = 0; d < 64; d++)
            acc = fmaf(xs[r][d], w1t[d * 130 + col], acc);
        if (col < 64) g_A[(row0 + r) * 64 + h] = acc;
        else          sc[h * 17 + r] = acc;
    }
    __syncthreads();

#pragma unroll
    for (int q = 0; q < 8; q++) {
        const int e = t * 8 + q;
        const int h2 = e >> 4, jl = e & 15;
        g_Ct[b * 65536 + h2 * 1024 + j0 + jl] = sc[h2 * 17 + jl];
    }
}

// ---------------------------------------------------------------------------
// K2: logits + softmax + attn + updated.  grid = B*64 = 256 blocks, 256 thr.
// TI=16 rows, TJ=128 per pass (8 passes).
// Phase 1 thread tile: 2i x 4j  (ti = t>>5 -> rows 2ti..2ti+1, tj = t&31)
// Phase 2: 4 j-groups (g = t>>6), each thread 4i x 4d outputs.
// ---------------------------------------------------------------------------
__global__ __launch_bounds__(256, 3) void k2_attn(const float* __restrict__ x,
                                                  const float* __restrict__ W2,
                                                  const float* __restrict__ b2,
                                                  float* __restrict__ upd,
                                                  float* __restrict__ attn)
{
    __shared__ float buf[8192];        // Ct tile [64][128] / x tile [128][64] / partials
    __shared__ float ps[16 * 128];     // prob tile
    __shared__ float At[64 * 18];      // A^T tile [h][i], stride 18
    __shared__ float2 w2d[64];         // {w,w}

    const int t  = threadIdx.x;
    const int b  = blockIdx.x >> 6;
    const int i0 = (blockIdx.x & 63) * 16;
    const int ti = t >> 5;            // 0..7 (warp id); rows 2ti, 2ti+1
    const int tj = t & 31;            // cols tj*4..tj*4+3
    const float b2v = b2[0];

    if (t < 64) { const float w = W2[t]; w2d[t] = make_float2(w, w); }
    {   // transpose A tile into At[h][i]
        const int il = t >> 4, h0 = (t & 15) * 4;
        float4 a4 = *(const float4*)&g_A[(b * Nk + i0 + il) * 64 + h0];
        At[(h0 + 0) * 18 + il] = a4.x;
        At[(h0 + 1) * 18 + il] = a4.y;
        At[(h0 + 2) * 18 + il] = a4.z;
        At[(h0 + 3) * 18 + il] = a4.w;
    }

    float m0 = -1e30f, m1 = -1e30f, s0 = 0.f, s1 = 0.f;
    const float* __restrict__ Ctb = g_Ct + b * 65536;
    float* __restrict__ attb = attn + (b * Nk + i0) * Nk;

    // ---------------- Phase 1: logits + online (m, s) ----------------
    for (int pass = 0; pass < 8; pass++) {
        const int jt = pass * 128;
        __syncthreads();
#pragma unroll
        for (int q = 0; q < 8; q++) {
            const int idx4 = q * 256 + t;
            const int row = idx4 >> 5, c4 = idx4 & 31;
            *(float4*)&buf[row * 128 + c4 * 4] =
                *(const float4*)&Ctb[row * 1024 + jt + c4 * 4];
        }
        __syncthreads();

        F2U al0, ah0, al1, ah1;
        al0.u = ah0.u = al1.u = ah1.u = 0ull;

#pragma unroll 4
        for (int h = 0; h < 64; h++) {
            const float2 a2 = *(const float2*)&At[h * 18 + ti * 2];
            const float4 c4 = *(const float4*)&buf[h * 128 + tj * 4];
            F2U wv; wv.f2 = w2d[h];
            F2U cl, ch; cl.f2 = make_float2(c4.x, c4.y); ch.f2 = make_float2(c4.z, c4.w);
            F2U ad0; ad0.f2 = make_float2(a2.x, a2.x);
            F2U ad1; ad1.f2 = make_float2(a2.y, a2.y);

            F2U v0; v0.u = add2(ad0.u, cl.u);
            v0.f[0] = fmaxf(v0.f[0], 0.f); v0.f[1] = fmaxf(v0.f[1], 0.f);
            al0.u = fma2(v0.u, wv.u, al0.u);

            F2U v1; v1.u = add2(ad0.u, ch.u);
            v1.f[0] = fmaxf(v1.f[0], 0.f); v1.f[1] = fmaxf(v1.f[1], 0.f);
            ah0.u = fma2(v1.u, wv.u, ah0.u);

            F2U v2; v2.u = add2(ad1.u, cl.u);
            v2.f[0] = fmaxf(v2.f[0], 0.f); v2.f[1] = fmaxf(v2.f[1], 0.f);
            al1.u = fma2(v2.u, wv.u, al1.u);

            F2U v3; v3.u = add2(ad1.u, ch.u);
            v3.f[0] = fmaxf(v3.f[0], 0.f); v3.f[1] = fmaxf(v3.f[1], 0.f);
            ah1.u = fma2(v3.u, wv.u, ah1.u);
        }

        float4 l0 = make_float4(al0.f[0] + b2v, al0.f[1] + b2v, ah0.f[0] + b2v, ah0.f[1] + b2v);
        float4 l1 = make_float4(al1.f[0] + b2v, al1.f[1] + b2v, ah1.f[0] + b2v, ah1.f[1] + b2v);
        *(float4*)&attb[(ti * 2 + 0) * Nk + jt + tj * 4] = l0;   // raw logits
        *(float4*)&attb[(ti * 2 + 1) * Nk + jt + tj * 4] = l1;

        {
            const float lm = fmaxf(fmaxf(l0.x, l0.y), fmaxf(l0.z, l0.w));
            const float mn = fmaxf(m0, lm);
            s0 = s0 * __expf(m0 - mn) + __expf(l0.x - mn) + __expf(l0.y - mn)
                                      + __expf(l0.z - mn) + __expf(l0.w - mn);
            m0 = mn;
        }
        {
            const float lm = fmaxf(fmaxf(l1.x, l1.y), fmaxf(l1.z, l1.w));
            const float mn = fmaxf(m1, lm);
            s1 = s1 * __expf(m1 - mn) + __expf(l1.x - mn) + __expf(l1.y - mn)
                                      + __expf(l1.z - mn) + __expf(l1.w - mn);
            m1 = mn;
        }
    }

    // each warp owns exactly rows {2*ti, 2*ti+1}: a full 32-lane reduce finishes them
#pragma unroll
    for (int off = 16; off > 0; off >>= 1) {
        float mo = __shfl_xor_sync(0xffffffffu, m0, off);
        float so = __shfl_xor_sync(0xffffffffu, s0, off);
        float mn = fmaxf(m0, mo);
        s0 = s0 * __expf(m0 - mn) + so * __expf(mo - mn);
        m0 = mn;
        mo = __shfl_xor_sync(0xffffffffu, m1, off);
        so = __shfl_xor_sync(0xffffffffu, s1, off);
        mn = fmaxf(m1, mo);
        s1 = s1 * __expf(m1 - mn) + so * __expf(mo - mn);
        m1 = mn;
    }
    const float is0 = 1.0f / s0;
    const float is1 = 1.0f / s1;

    // ---------------- Phase 2: normalize attn + updated = attn @ x ----------
    const int g   = t >> 6;            // j-group
    const int t6  = t & 63;
    const int ti2 = t6 >> 4;           // rows ti2*4 .. ti2*4+3
    const int dg  = t6 & 15;           // d cols dg*4 .. dg*4+3
    const int jb  = g * 32;
    const float* __restrict__ xb = x + b * Nk * 64;

    F2U ul[4], uh[4];
#pragma unroll
    for (int ii = 0; ii < 4; ii++) { ul[ii].u = 0ull; uh[ii].u = 0ull; }

    for (int pass = 0; pass < 8; pass++) {
        const int jt = pass * 128;
        __syncthreads();
        // x tile [128][64]
#pragma unroll
        for (int q = 0; q < 8; q++) {
            const int idx4 = q * 256 + t;
            const int j = idx4 >> 4, d4 = idx4 & 15;
            *(float4*)&buf[j * 64 + d4 * 4] =
                *(const float4*)&xb[(jt + j) * 64 + d4 * 4];
        }
        // probabilities for this pass (phase-1 thread mapping; own logits)
#pragma unroll
        for (int r = 0; r < 2; r++) {
            const int row = ti * 2 + r;
            const float mi = r ? m1 : m0;
            const float si = r ? is1 : is0;
            float4 l4 = *(const float4*)&attb[row * Nk + jt + tj * 4];
            float4 p;
            p.x = __expf(l4.x - mi) * si;
            p.y = __expf(l4.y - mi) * si;
            p.z = __expf(l4.z - mi) * si;
            p.w = __expf(l4.w - mi) * si;
            *(float4*)&attb[row * Nk + jt + tj * 4] = p;   // final attn
            *(float4*)&ps[row * 128 + tj * 4] = p;
        }
        __syncthreads();

#pragma unroll 2
        for (int jj = 0; jj < 32; jj++) {
            const float4 x4 = *(const float4*)&buf[(jb + jj) * 64 + dg * 4];
            F2U xl, xh; xl.f2 = make_float2(x4.x, x4.y); xh.f2 = make_float2(x4.z, x4.w);
#pragma unroll
            for (int ii = 0; ii < 4; ii++) {
                const float p = ps[(ti2 * 4 + ii) * 128 + jb + jj];
                F2U pd; pd.f2 = make_float2(p, p);
                ul[ii].u = fma2(pd.u, xl.u, ul[ii].u);
                uh[ii].u = fma2(pd.u, xh.u, uh[ii].u);
            }
        }
    }

    // reduce the 4 j-group partials through smem
    __syncthreads();
#pragma unroll
    for (int ii = 0; ii < 4; ii++) {
        const int row = ti2 * 4 + ii;
        float4 v = make_float4(ul[ii].f[0], ul[ii].f[1], uh[ii].f[0], uh[ii].f[1]);
        *(float4*)&buf[(row * 4 + g) * 64 + dg * 4] = v;
    }
    __syncthreads();
    {
        const int rowr = t >> 4, dq = (t & 15) * 4;
        float4 v0 = *(const float4*)&buf[(rowr * 4 + 0) * 64 + dq];
        float4 v1 = *(const float4*)&buf[(rowr * 4 + 1) * 64 + dq];
        float4 v2 = *(const float4*)&buf[(rowr * 4 + 2) * 64 + dq];
        float4 v3 = *(const float4*)&buf[(rowr * 4 + 3) * 64 + dq];
        float4 s;
        s.x = (v0.x + v1.x) + (v2.x + v3.x);
        s.y = (v0.y + v1.y) + (v2.y + v3.y);
        s.z = (v0.z + v1.z) + (v2.z + v3.z);
        s.w = (v0.w + v1.w) + (v2.w + v3.w);
        *(float4*)&upd[(b * Nk + i0 + rowr) * 64 + dq] = s;
    }
}

// ---------------------------------------------------------------------------
extern "C" void kernel_launch(void* const* d_in, const int* in_sizes, int n_in,
                              void* d_out, int out_size)
{
    const float* x  = (const float*)d_in[0];
    const float* W1 = (const float*)d_in[1];
    const float* b1 = (const float*)d_in[2];
    const float* W2 = (const float*)d_in[3];
    const float* b2 = (const float*)d_in[4];

    float* upd  = (float*)d_out;                    // (B,N,H)
    float* attn = (float*)d_out + Bk * Nk * 64;     // (B,N,N)

    k1_proj<<<(Bk * Nk) / 16, 128>>>(x, W1, b1);
    k2_attn<<<Bk * 64, 256>>>(x, W2, b2, upd, attn);
}

// round 7
// speedup vs baseline: 1.6456x; 1.0346x over previous
#include <cuda_runtime.h>
#include <math.h>

// B=4, N=1024, H=64
// in: x (B,N,H) f32, W1 (H,2H) f32, b1 (H) f32, W2 (1,H) f32, b2 (1) f32
// out: updated (B,N,H) f32 ++ attn (B,N,N) f32

#define Bk 4
#define Nk 1024

// scratch
__device__ float  g_A[Bk * Nk * 64];    // A[b*N+i][h] = x@W1a^T + b1
__device__ float  g_Ct[Bk * 64 * Nk];   // C^T: [b][h][j]
__device__ float2 g_ms[Bk * Nk * 4];    // per (row, j-chunk): (m, s)

union F2U { float2 f2; unsigned long long u; float f[2]; };

__device__ __forceinline__ unsigned long long add2(unsigned long long a, unsigned long long b) {
    unsigned long long r;
    asm("add.rn.f32x2 %0, %1, %2;" : "=l"(r) : "l"(a), "l"(b));
    return r;
}
__device__ __forceinline__ unsigned long long fma2(unsigned long long a, unsigned long long b,
                                                   unsigned long long c) {
    unsigned long long r;
    asm("fma.rn.f32x2 %0, %1, %2, %3;" : "=l"(r) : "l"(a), "l"(b), "l"(c));
    return r;
}

// ---------------------------------------------------------------------------
// K1: projections. grid = B*N/8 = 512 blocks, 128 threads.
// Thread t owns output column t (t<64 -> A col h=t; t>=64 -> C col h=t-64).
// W1 row held in registers; x rows broadcast from smem.
// ---------------------------------------------------------------------------
__global__ __launch_bounds__(128) void k1_proj(const float* __restrict__ x,
                                               const float* __restrict__ W1,
                                               const float* __restrict__ b1)
{
    __shared__ float xs[8 * 64];
    __shared__ float sc[64 * 9];      // C staging for transposed writeout

    const int t = threadIdx.x;
    const int row0 = blockIdx.x * 8;
    const int b = row0 >> 10;
    const int j0 = row0 & 1023;

    // stage 8 x rows
    *(float4*)&xs[t * 4] = ((const float4*)x)[row0 * 16 + t];

    // W1 row into registers (64 floats as 32 f32x2)
    const int h = t & 63;
    const int offq = (t < 64) ? 0 : 16;          // float4 offset within row
    F2U wr[32];
    const float4* __restrict__ W1v = (const float4*)W1;
#pragma unroll
    for (int q = 0; q < 16; q++) {
        float4 v = W1v[h * 32 + offq + q];
        wr[2 * q + 0].f2 = make_float2(v.x, v.y);
        wr[2 * q + 1].f2 = make_float2(v.z, v.w);
    }
    const float bias = (t < 64) ? b1[h] : 0.0f;
    __syncthreads();

#pragma unroll
    for (int r = 0; r < 8; r++) {
        F2U acc; acc.u = 0ull;
#pragma unroll
        for (int q = 0; q < 16; q++) {
            const float4 x4 = *(const float4*)&xs[r * 64 + q * 4];
            F2U xa, xb; xa.f2 = make_float2(x4.x, x4.y); xb.f2 = make_float2(x4.z, x4.w);
            acc.u = fma2(xa.u, wr[2 * q + 0].u, acc.u);
            acc.u = fma2(xb.u, wr[2 * q + 1].u, acc.u);
        }
        const float v = acc.f[0] + acc.f[1] + bias;
        if (t < 64) g_A[(row0 + r) * 64 + h] = v;
        else        sc[h * 9 + r] = v;
    }
    __syncthreads();

#pragma unroll
    for (int q = 0; q < 4; q++) {
        const int e = t * 4 + q;
        const int h2 = e >> 3, jl = e & 7;
        g_Ct[b * 65536 + h2 * 1024 + j0 + jl] = sc[h2 * 9 + jl];
    }
}

// ---------------------------------------------------------------------------
// K2a: logits + per-chunk (m,s).  grid = B*64*4 = 1024 blocks, 256 threads.
// Block: 16 i-rows x 256 j (one chunk).  Thread tile 4i x 4j.
// C read directly from global (L1-resident chunk), A^T + W2 in smem.
// ---------------------------------------------------------------------------
__global__ __launch_bounds__(256, 3) void k2a_logits(const float* __restrict__ W2,
                                                     const float* __restrict__ b2,
                                                     float* __restrict__ attn)
{
    __shared__ float At[64 * 20];      // A^T [h][i], stride 20
    __shared__ float2 w2d[64];
    __shared__ float redm[8 * 4];
    __shared__ float reds[8 * 4];

    const int t = threadIdx.x;
    const int bid = blockIdx.x;
    const int b     = bid >> 8;
    const int itile = (bid >> 2) & 63;
    const int chunk = bid & 3;
    const int i0 = itile * 16;
    const int j0 = chunk * 256;

    const int ti = t >> 6;            // i-group: rows ti*4..ti*4+3
    const int tj = t & 63;            // j-quad: cols j0 + tj*4 ..

    if (t < 64) { const float w = W2[t]; w2d[t] = make_float2(w, w); }
    {   // A^T tile
        const int il = t >> 4, h0 = (t & 15) * 4;
        float4 a4 = *(const float4*)&g_A[(b * Nk + i0 + il) * 64 + h0];
        At[(h0 + 0) * 20 + il] = a4.x;
        At[(h0 + 1) * 20 + il] = a4.y;
        At[(h0 + 2) * 20 + il] = a4.z;
        At[(h0 + 3) * 20 + il] = a4.w;
    }
    __syncthreads();

    const float* __restrict__ Cc = g_Ct + b * 65536 + j0 + tj * 4;
    F2U accl[4], acch[4];
#pragma unroll
    for (int ii = 0; ii < 4; ii++) { accl[ii].u = 0ull; acch[ii].u = 0ull; }

#pragma unroll 8
    for (int h = 0; h < 64; h++) {
        const float4 c4 = *(const float4*)&Cc[h * 1024];
        const float4 a4 = *(const float4*)&At[h * 20 + ti * 4];
        F2U wv; wv.f2 = w2d[h];
        F2U cl, ch; cl.f2 = make_float2(c4.x, c4.y); ch.f2 = make_float2(c4.z, c4.w);
        const float av[4] = {a4.x, a4.y, a4.z, a4.w};
#pragma unroll
        for (int ii = 0; ii < 4; ii++) {
            F2U ad; ad.f2 = make_float2(av[ii], av[ii]);
            F2U v0; v0.u = add2(ad.u, cl.u);
            v0.f[0] = fmaxf(v0.f[0], 0.f); v0.f[1] = fmaxf(v0.f[1], 0.f);
            accl[ii].u = fma2(v0.u, wv.u, accl[ii].u);
            F2U v1; v1.u = add2(ad.u, ch.u);
            v1.f[0] = fmaxf(v1.f[0], 0.f); v1.f[1] = fmaxf(v1.f[1], 0.f);
            acch[ii].u = fma2(v1.u, wv.u, acch[ii].u);
        }
    }

    const float b2v = b2[0];
    float* __restrict__ attb = attn + (b * Nk + i0) * Nk + j0;
    float m[4], s[4];
#pragma unroll
    for (int ii = 0; ii < 4; ii++) {
        float4 l4 = make_float4(accl[ii].f[0] + b2v, accl[ii].f[1] + b2v,
                                acch[ii].f[0] + b2v, acch[ii].f[1] + b2v);
        *(float4*)&attb[(ti * 4 + ii) * Nk + tj * 4] = l4;     // raw logits
        const float lm = fmaxf(fmaxf(l4.x, l4.y), fmaxf(l4.z, l4.w));
        m[ii] = lm;
        s[ii] = __expf(l4.x - lm) + __expf(l4.y - lm)
              + __expf(l4.z - lm) + __expf(l4.w - lm);
    }

    // reduce over the 32 lanes of each warp (warp covers rows ti*4..+3, half the j's)
#pragma unroll
    for (int off = 16; off > 0; off >>= 1) {
#pragma unroll
        for (int ii = 0; ii < 4; ii++) {
            const float mo = __shfl_xor_sync(0xffffffffu, m[ii], off);
            const float so = __shfl_xor_sync(0xffffffffu, s[ii], off);
            const float mn = fmaxf(m[ii], mo);
            s[ii] = s[ii] * __expf(m[ii] - mn) + so * __expf(mo - mn);
            m[ii] = mn;
        }
    }
    const int w = t >> 5;
    if ((t & 31) == 0) {
#pragma unroll
        for (int ii = 0; ii < 4; ii++) { redm[w * 4 + ii] = m[ii]; reds[w * 4 + ii] = s[ii]; }
    }
    __syncthreads();
    if (t < 16) {     // row r = t; merge warps 2*(r>>2) and 2*(r>>2)+1
        const int tig = t >> 2, ii = t & 3;
        const float mA = redm[(2 * tig) * 4 + ii], mB = redm[(2 * tig + 1) * 4 + ii];
        const float mn = fmaxf(mA, mB);
        const float ss = reds[(2 * tig) * 4 + ii] * __expf(mA - mn)
                       + reds[(2 * tig + 1) * 4 + ii] * __expf(mB - mn);
        g_ms[(b * Nk + i0 + t) * 4 + chunk] = make_float2(mn, ss);
    }
}

// ---------------------------------------------------------------------------
// K2b: merge (m,s), normalize attn, updated = attn @ x.
// grid = B*64 = 256 blocks, 256 threads. 8 passes of 128 j.
// GEMM thread tile: 4 j-groups (g), each thread 4i x 4d.
// ---------------------------------------------------------------------------
__global__ __launch_bounds__(256, 2) void k2b_av(const float* __restrict__ x,
                                                 float* __restrict__ upd,
                                                 float* __restrict__ attn)
{
    __shared__ float  xs[128 * 68];    // x tile (also reused for final reduction)
    __shared__ float2 psd[16 * 128];   // {p,p} duplicated probabilities
    __shared__ float  smm[16], sis[16];

    const int t = threadIdx.x;
    const int b  = blockIdx.x >> 6;
    const int i0 = (blockIdx.x & 63) * 16;

    if (t < 16) {   // merge 4 chunk partials for row i0+t
        const float2* msr = &g_ms[(b * Nk + i0 + t) * 4];
        float2 c0 = msr[0], c1 = msr[1], c2 = msr[2], c3 = msr[3];
        float mn = fmaxf(fmaxf(c0.x, c1.x), fmaxf(c2.x, c3.x));
        float ss = c0.y * __expf(c0.x - mn) + c1.y * __expf(c1.x - mn)
                 + c2.y * __expf(c2.x - mn) + c3.y * __expf(c3.x - mn);
        smm[t] = mn;
        sis[t] = 1.0f / ss;
    }

    const int g   = t >> 6;
    const int t6  = t & 63;
    const int ti2 = t6 >> 4;          // rows ti2*4..+3
    const int dg  = t6 & 15;          // d cols dg*4..+3
    const int jb  = g * 32;
    const int prow = t >> 4;          // p-compute: row
    const int pjo  = (t & 15) * 8;    // p-compute: j offset

    const float* __restrict__ xb = x + b * Nk * 64;
    float* __restrict__ attb = attn + (b * Nk + i0) * Nk;

    F2U ul[4], uh[4];
#pragma unroll
    for (int ii = 0; ii < 4; ii++) { ul[ii].u = 0ull; uh[ii].u = 0ull; }

    for (int pass = 0; pass < 8; pass++) {
        const int jt = pass * 128;
        __syncthreads();
        // stage x tile [128][64] (padded 68)
#pragma unroll
        for (int q = 0; q < 8; q++) {
            const int idx4 = q * 256 + t;
            const int j = idx4 >> 4, d4 = idx4 & 15;
            *(float4*)&xs[j * 68 + d4 * 4] =
                *(const float4*)&xb[(jt + j) * 64 + d4 * 4];
        }
        // probabilities: 8 logits per thread
        {
            const float mi = smm[prow], si = sis[prow];
            float4 l0 = *(const float4*)&attb[prow * Nk + jt + pjo];
            float4 l1 = *(const float4*)&attb[prow * Nk + jt + pjo + 4];
            float4 p0, p1;
            p0.x = __expf(l0.x - mi) * si;  p0.y = __expf(l0.y - mi) * si;
            p0.z = __expf(l0.z - mi) * si;  p0.w = __expf(l0.w - mi) * si;
            p1.x = __expf(l1.x - mi) * si;  p1.y = __expf(l1.y - mi) * si;
            p1.z = __expf(l1.z - mi) * si;  p1.w = __expf(l1.w - mi) * si;
            *(float4*)&attb[prow * Nk + jt + pjo]     = p0;   // final attn
            *(float4*)&attb[prow * Nk + jt + pjo + 4] = p1;
            float2* pd = &psd[prow * 128 + pjo];
            pd[0] = make_float2(p0.x, p0.x);  pd[1] = make_float2(p0.y, p0.y);
            pd[2] = make_float2(p0.z, p0.z);  pd[3] = make_float2(p0.w, p0.w);
            pd[4] = make_float2(p1.x, p1.x);  pd[5] = make_float2(p1.y, p1.y);
            pd[6] = make_float2(p1.z, p1.z);  pd[7] = make_float2(p1.w, p1.w);
        }
        __syncthreads();

#pragma unroll 4
        for (int jj = 0; jj < 32; jj++) {
            const float4 x4 = *(const float4*)&xs[(jb + jj) * 68 + dg * 4];
            F2U xl, xh; xl.f2 = make_float2(x4.x, x4.y); xh.f2 = make_float2(x4.z, x4.w);
#pragma unroll
            for (int ii = 0; ii < 4; ii++) {
                const unsigned long long p2 =
                    *(const unsigned long long*)&psd[(ti2 * 4 + ii) * 128 + jb + jj];
                ul[ii].u = fma2(p2, xl.u, ul[ii].u);
                uh[ii].u = fma2(p2, xh.u, uh[ii].u);
            }
        }
    }

    // reduce 4 g-partials (deterministic order) via smem, then store updated
    __syncthreads();
#pragma unroll
    for (int ii = 0; ii < 4; ii++) {
        const int row = ti2 * 4 + ii;
        float4 v = make_float4(ul[ii].f[0], ul[ii].f[1], uh[ii].f[0], uh[ii].f[1]);
        *(float4*)&xs[((row * 4 + g) * 64) + dg * 4] = v;
    }
    __syncthreads();
    {
        const int rowr = t >> 4, dq = (t & 15) * 4;
        float4 v0 = *(const float4*)&xs[(rowr * 4 + 0) * 64 + dq];
        float4 v1 = *(const float4*)&xs[(rowr * 4 + 1) * 64 + dq];
        float4 v2 = *(const float4*)&xs[(rowr * 4 + 2) * 64 + dq];
        float4 v3 = *(const float4*)&xs[(rowr * 4 + 3) * 64 + dq];
        float4 sv;
        sv.x = (v0.x + v1.x) + (v2.x + v3.x);
        sv.y = (v0.y + v1.y) + (v2.y + v3.y);
        sv.z = (v0.z + v1.z) + (v2.z + v3.z);
        sv.w = (v0.w + v1.w) + (v2.w + v3.w);
        *(float4*)&upd[(b * Nk + i0 + rowr) * 64 + dq] = sv;
    }
}

// ---------------------------------------------------------------------------
extern "C" void kernel_launch(void* const* d_in, const int* in_sizes, int n_in,
                              void* d_out, int out_size)
{
    const float* x  = (const float*)d_in[0];
    const float* W1 = (const float*)d_in[1];
    const float* b1 = (const float*)d_in[2];
    const float* W2 = (const float*)d_in[3];
    const float* b2 = (const float*)d_in[4];

    float* upd  = (float*)d_out;                    // (B,N,H)
    float* attn = (float*)d_out + Bk * Nk * 64;     // (B,N,N)

    k1_proj<<<(Bk * Nk) / 8, 128>>>(x, W1, b1);
    k2a_logits<<<Bk * 64 * 4, 256>>>(W2, b2, attn);
    k2b_av<<<Bk * 64, 256>>>(x, upd, attn);
}